// round 15
// baseline (speedup 1.0000x reference)
#include <cuda_runtime.h>
#include <cuda_fp16.h>
#include <cstdint>

#define NN   50000
#define IN_F 256
#define AD   128
#define NH   8
#define NE   1600000

// Scratch
__device__ __half g_qh[(size_t)NN * AD];     // 12.8 MB  q fp16
__device__ __half g_kh[(size_t)NN * AD];     // 12.8 MB  k fp16
__device__ float  g_sum[NN * NH];            // 1.6 MB
__device__ __half g_wf[2 * AD * IN_F];       // 128 KB   Qw|Kw fp16

// ---------------------------------------------------------------------------
// Prep-lite: convert Qw|Kw to fp16; zero g_sum.
// ---------------------------------------------------------------------------
#define PREP_W   (2 * AD * 64)
#define PREP_S   (NN * NH / 4)
#define PREP_TOT (PREP_W + PREP_S)

__device__ __forceinline__ uint2 cvt4(float4 v) {
    __half2 a = __floats2half2_rn(v.x, v.y);
    __half2 b = __floats2half2_rn(v.z, v.w);
    uint2 r;
    r.x = *(uint32_t*)&a;
    r.y = *(uint32_t*)&b;
    return r;
}

__global__ void prep_kernel(const float* __restrict__ Qw,
                            const float* __restrict__ Kw) {
    int idx = blockIdx.x * blockDim.x + threadIdx.x;
    if (idx < PREP_W) {
        int m = idx >> 13;
        int r = idx & 8191;
        ((uint2*)g_wf)[(size_t)m * 8192 + r] = cvt4(((const float4*)(m ? Kw : Qw))[r]);
    } else if (idx < PREP_TOT) {
        ((float4*)g_sum)[idx - PREP_W] = make_float4(0.f, 0.f, 0.f, 0.f);
    }
}

// ---------------------------------------------------------------------------
// Tensor-core helpers (fp16 mma)
// ---------------------------------------------------------------------------
__device__ __forceinline__ void ldsm_x4(uint32_t& r0, uint32_t& r1,
                                        uint32_t& r2, uint32_t& r3,
                                        uint32_t addr) {
    asm volatile("ldmatrix.sync.aligned.m8n8.x4.shared.b16 {%0,%1,%2,%3}, [%4];"
                 : "=r"(r0), "=r"(r1), "=r"(r2), "=r"(r3) : "r"(addr));
}
__device__ __forceinline__ void ldsm_x2(uint32_t& r0, uint32_t& r1,
                                        uint32_t addr) {
    asm volatile("ldmatrix.sync.aligned.m8n8.x2.shared.b16 {%0,%1}, [%2];"
                 : "=r"(r0), "=r"(r1) : "r"(addr));
}
__device__ __forceinline__ void mma_f16(float& c0, float& c1, float& c2, float& c3,
                                        uint32_t a0, uint32_t a1, uint32_t a2, uint32_t a3,
                                        uint32_t b0, uint32_t b1) {
    asm volatile("mma.sync.aligned.m16n8k16.row.col.f32.f16.f16.f32 "
                 "{%0,%1,%2,%3}, {%4,%5,%6,%7}, {%8,%9}, {%0,%1,%2,%3};"
                 : "+f"(c0), "+f"(c1), "+f"(c2), "+f"(c3)
                 : "r"(a0), "r"(a1), "r"(a2), "r"(a3), "r"(b0), "r"(b1));
}

// ---------------------------------------------------------------------------
// Fused Q|K projection GEMM (unchanged from R14).
// ---------------------------------------------------------------------------
#define KP 40

__global__ __launch_bounds__(512) void proj_mma_kernel(const float* __restrict__ hi,
                                                       const float* __restrict__ Qb,
                                                       const float* __restrict__ Kb) {
    const uint4* Wg = (const uint4*)g_wf;

    __shared__ __half As[128][KP];
    __shared__ __half Ws[256][KP];

    const int tid  = threadIdx.x;
    const int lane = tid & 31;
    const int wid  = tid >> 5;
    const int wm   = wid & 3;
    const int wn   = wid >> 2;
    const int m0   = blockIdx.x * 128;

    float c[2][8][4];
#pragma unroll
    for (int mt = 0; mt < 2; mt++)
#pragma unroll
        for (int nt = 0; nt < 8; nt++)
#pragma unroll
            for (int i = 0; i < 4; i++) c[mt][nt][i] = 0.0f;

    const int alrow = tid >> 2;
    const int alq   = tid & 3;
    int arow_g = m0 + alrow;
    if (arow_g >= NN) arow_g = NN - 1;
    const float4* hi4 = (const float4*)hi;
    const size_t a_base = (size_t)arow_g * 64 + alq * 2;

    const int wlrow = tid >> 1;
    const int wlh   = tid & 1;
    const size_t w_base = (size_t)wlrow * 32 + wlh * 2;

    const int a_row  = wm * 32 + (lane & 15);
    const int a_koff = (lane >> 4) * 8;
    const int b_row  = wn * 64 + (lane & 7);
    const int b_koff = ((lane >> 3) & 1) * 8;

    float4 pa0, pa1;
    uint4  pw0, pw1;
    pa0 = hi4[a_base];  pa1 = hi4[a_base + 1];
    pw0 = Wg[w_base];   pw1 = Wg[w_base + 1];

    for (int ch = 0; ch < 8; ch++) {
        {
            uint2 h0 = cvt4(pa0), h1 = cvt4(pa1);
            uint4 v; v.x = h0.x; v.y = h0.y; v.z = h1.x; v.w = h1.y;
            *(uint4*)&As[alrow][alq * 8] = v;
            *(uint4*)&Ws[wlrow][wlh * 16]     = pw0;
            *(uint4*)&Ws[wlrow][wlh * 16 + 8] = pw1;
        }
        __syncthreads();

        if (ch < 7) {
            const int kc4 = (ch + 1) * 8;
            pa0 = hi4[a_base + kc4];
            pa1 = hi4[a_base + kc4 + 1];
            pw0 = Wg[w_base + (ch + 1) * 4];
            pw1 = Wg[w_base + (ch + 1) * 4 + 1];
        }

#pragma unroll
        for (int ks = 0; ks < 2; ks++) {
            const int k0 = ks * 16;
            uint32_t a[2][4];
#pragma unroll
            for (int mt = 0; mt < 2; mt++) {
                uint32_t addr = (uint32_t)__cvta_generic_to_shared(
                    &As[a_row + mt * 16][k0 + a_koff]);
                ldsm_x4(a[mt][0], a[mt][1], a[mt][2], a[mt][3], addr);
            }
#pragma unroll
            for (int nt = 0; nt < 8; nt++) {
                uint32_t b0, b1;
                uint32_t baddr = (uint32_t)__cvta_generic_to_shared(
                    &Ws[b_row + nt * 8][k0 + b_koff]);
                ldsm_x2(b0, b1, baddr);
#pragma unroll
                for (int mt = 0; mt < 2; mt++) {
                    mma_f16(c[mt][nt][0], c[mt][nt][1], c[mt][nt][2], c[mt][nt][3],
                            a[mt][0], a[mt][1], a[mt][2], a[mt][3], b0, b1);
                }
            }
        }
        __syncthreads();
    }

    __half* out        = (wn < 2) ? g_qh : g_kh;
    const float* bias  = (wn < 2) ? Qb   : Kb;
    const int colbase  = (wn & 1) * 64;
#pragma unroll
    for (int nt = 0; nt < 8; nt++) {
        const int col = colbase + nt * 8 + (lane & 3) * 2;
        const float b0 = __ldg(&bias[col]);
        const float b1 = __ldg(&bias[col + 1]);
#pragma unroll
        for (int mt = 0; mt < 2; mt++) {
            const int r0 = m0 + wm * 32 + mt * 16 + (lane >> 2);
            if (r0 < NN) {
                *(__half2*)&out[(size_t)r0 * AD + col] =
                    __floats2half2_rn(c[mt][nt][0] + b0, c[mt][nt][1] + b1);
            }
            const int r1 = r0 + 8;
            if (r1 < NN) {
                *(__half2*)&out[(size_t)r1 * AD + col] =
                    __floats2half2_rn(c[mt][nt][2] + b0, c[mt][nt][3] + b1);
            }
        }
    }
}

// ---------------------------------------------------------------------------
// Edge pass: warp per 8 edges, paired-lane LDG.128.
// Output src index now obtained via shuffles of msrc (no edge[] reload).
// ---------------------------------------------------------------------------
__global__ __launch_bounds__(256) void edge_kernel(const float* __restrict__ radial,
                                                   const int*  __restrict__ edge,
                                                   const float* __restrict__ Qrw,
                                                   const float* __restrict__ Qrb,
                                                   float* __restrict__ prods) {
    const int lane = threadIdx.x & 31;
    const int gw   = (blockIdx.x * 256 + threadIdx.x) >> 5;
    const int e0   = gw * 8;
    const int side = lane >> 4;
    const int sub  = lane & 15;

    float w8[8], b8[8];
    {
        const float4* w4p = (const float4*)Qrw;
        const float4* b4p = (const float4*)Qrb;
        float4 wa = w4p[sub * 2], wb = w4p[sub * 2 + 1];
        float4 ba = b4p[sub * 2], bb = b4p[sub * 2 + 1];
        w8[0]=wa.x; w8[1]=wa.y; w8[2]=wa.z; w8[3]=wa.w;
        w8[4]=wb.x; w8[5]=wb.y; w8[6]=wb.z; w8[7]=wb.w;
        b8[0]=ba.x; b8[1]=ba.y; b8[2]=ba.z; b8[3]=ba.w;
        b8[4]=bb.x; b8[5]=bb.y; b8[6]=bb.z; b8[7]=bb.w;
    }

    int   msrc[4], mdst[4];
    float mr[4];
#pragma unroll
    for (int s = 0; s < 4; s++) {
        int e = e0 + 2 * s + side;
        msrc[s] = edge[e];
        mdst[s] = edge[NE + e];
        mr[s]   = radial[e];
    }

    uint4 qv[4], kv[4];
#pragma unroll
    for (int s = 0; s < 4; s++) {
        qv[s] = *(const uint4*)(g_qh + (size_t)msrc[s] * AD + sub * 8);
        kv[s] = *(const uint4*)(g_kh + (size_t)mdst[s] * AD + sub * 8);
    }

    float t[4];
#pragma unroll
    for (int s = 0; s < 4; s++) {
        const uint32_t* qw = (const uint32_t*)&qv[s];
        const uint32_t* kw = (const uint32_t*)&kv[s];
        float acc = 0.f;
        const float r = mr[s];
#pragma unroll
        for (int p = 0; p < 4; p++) {
            float2 q2 = __half22float2(*(const __half2*)&qw[p]);
            float2 k2 = __half22float2(*(const __half2*)&kw[p]);
            float s0 = q2.x + fmaf(r, w8[2 * p],     b8[2 * p]);
            float s1 = q2.y + fmaf(r, w8[2 * p + 1], b8[2 * p + 1]);
            acc = fmaf(s0, k2.x, acc);
            acc = fmaf(s1, k2.y, acc);
        }
        acc += __shfl_xor_sync(0xffffffff, acc, 1);
        t[s] = acc;
    }

    // lane l -> (edge e0+4r+j, head l&7), j = l>>3; slot = 2r+(j>>1), side = j&1
    const int j     = lane >> 3;
    const int l_src = (j & 1) * 16 + 2 * (lane & 7);
    const int l_meta = (j & 1) * 16;              // any lane of matching side
#pragma unroll
    for (int r = 0; r < 2; r++) {
        const float va = __shfl_sync(0xffffffff, t[2 * r],     l_src);
        const float vb = __shfl_sync(0xffffffff, t[2 * r + 1], l_src);
        const float pr = ((j >> 1) ? vb : va) * 0.25f;

        prods[(e0 + 4 * r) * NH + lane] = pr;
        const float ex = __expf(pr);

        const int s0 = __shfl_sync(0xffffffff, msrc[2 * r],     l_meta);
        const int s1 = __shfl_sync(0xffffffff, msrc[2 * r + 1], l_meta);
        const int se = (j >> 1) ? s1 : s0;
        atomicAdd(&g_sum[se * NH + (lane & 7)], ex);
    }
}

// ---------------------------------------------------------------------------
// Norm: 2 edges (4 float4) per thread — MLP ~10, 4x fewer instructions.
// att[e,h] = exp(prods[e,h]) / sum[src,h]
// ---------------------------------------------------------------------------
__global__ __launch_bounds__(256) void norm_kernel(const int* __restrict__ edge,
                                                   const float* __restrict__ prods,
                                                   float* __restrict__ att) {
    int t = blockIdx.x * blockDim.x + threadIdx.x;     // < NE/2
    if (t < NE / 2) {
        const int2 ep = ((const int2*)edge)[t];        // edges 2t, 2t+1
        const float4* sp0 = (const float4*)&g_sum[ep.x * NH];
        const float4* sp1 = (const float4*)&g_sum[ep.y * NH];
        float4 s00 = sp0[0], s01 = sp0[1];
        float4 s10 = sp1[0], s11 = sp1[1];

        const float4* pp = (const float4*)prods + (size_t)t * 4;
        float4 p0 = pp[0], p1 = pp[1], p2 = pp[2], p3 = pp[3];

        float4 a0, a1, a2, a3;
        a0.x = __fdividef(__expf(p0.x), s00.x);
        a0.y = __fdividef(__expf(p0.y), s00.y);
        a0.z = __fdividef(__expf(p0.z), s00.z);
        a0.w = __fdividef(__expf(p0.w), s00.w);
        a1.x = __fdividef(__expf(p1.x), s01.x);
        a1.y = __fdividef(__expf(p1.y), s01.y);
        a1.z = __fdividef(__expf(p1.z), s01.z);
        a1.w = __fdividef(__expf(p1.w), s01.w);
        a2.x = __fdividef(__expf(p2.x), s10.x);
        a2.y = __fdividef(__expf(p2.y), s10.y);
        a2.z = __fdividef(__expf(p2.z), s10.z);
        a2.w = __fdividef(__expf(p2.w), s10.w);
        a3.x = __fdividef(__expf(p3.x), s11.x);
        a3.y = __fdividef(__expf(p3.y), s11.y);
        a3.z = __fdividef(__expf(p3.z), s11.z);
        a3.w = __fdividef(__expf(p3.w), s11.w);

        float4* ap = (float4*)att + (size_t)t * 4;
        ap[0] = a0; ap[1] = a1; ap[2] = a2; ap[3] = a3;
    }
}

// ---------------------------------------------------------------------------
extern "C" void kernel_launch(void* const* d_in, const int* in_sizes, int n_in,
                              void* d_out, int out_size) {
    const float* hi     = (const float*)d_in[0];
    const float* radial = (const float*)d_in[1];
    const float* Qw     = (const float*)d_in[2];
    const float* Qb     = (const float*)d_in[3];
    const float* Qrw    = (const float*)d_in[4];
    const float* Qrb    = (const float*)d_in[5];
    const float* Kw     = (const float*)d_in[6];
    const float* Kb     = (const float*)d_in[7];
    const int*   edge   = (const int*)d_in[8];

    float* out   = (float*)d_out;
    float* att   = out;                       // [E, H]
    float* prods = out + (size_t)NE * NH;     // [E, H]

    prep_kernel<<<(PREP_TOT + 255) / 256, 256>>>(Qw, Kw);
    proj_mma_kernel<<<(NN + 127) / 128, 512>>>(hi, Qb, Kb);
    edge_kernel<<<NE / 64, 256>>>(radial, edge, Qrw, Qrb, prods);
    norm_kernel<<<(NE / 2 + 255) / 256, 256>>>(edge, prods, att);
}

// round 16
// speedup vs baseline: 1.0566x; 1.0566x over previous
#include <cuda_runtime.h>
#include <cuda_fp16.h>
#include <cstdint>

#define NN   50000
#define IN_F 256
#define AD   128
#define NH   8
#define NE   1600000

// Scratch
__device__ __half g_qh[(size_t)NN * AD];     // 12.8 MB  q fp16
__device__ __half g_kh[(size_t)NN * AD];     // 12.8 MB  k fp16
__device__ float  g_sum[NN * NH];            // 1.6 MB
__device__ __half g_wf[2 * AD * IN_F];       // 128 KB   Qw|Kw fp16

// ---------------------------------------------------------------------------
// Prep-lite: convert Qw|Kw to fp16; zero g_sum.
// ---------------------------------------------------------------------------
#define PREP_W   (2 * AD * 64)
#define PREP_S   (NN * NH / 4)
#define PREP_TOT (PREP_W + PREP_S)

__device__ __forceinline__ uint2 cvt4(float4 v) {
    __half2 a = __floats2half2_rn(v.x, v.y);
    __half2 b = __floats2half2_rn(v.z, v.w);
    uint2 r;
    r.x = *(uint32_t*)&a;
    r.y = *(uint32_t*)&b;
    return r;
}

__global__ void prep_kernel(const float* __restrict__ Qw,
                            const float* __restrict__ Kw) {
    int idx = blockIdx.x * blockDim.x + threadIdx.x;
    if (idx < PREP_W) {
        int m = idx >> 13;
        int r = idx & 8191;
        ((uint2*)g_wf)[(size_t)m * 8192 + r] = cvt4(((const float4*)(m ? Kw : Qw))[r]);
    } else if (idx < PREP_TOT) {
        ((float4*)g_sum)[idx - PREP_W] = make_float4(0.f, 0.f, 0.f, 0.f);
    }
}

// ---------------------------------------------------------------------------
// Tensor-core helpers (fp16 mma)
// ---------------------------------------------------------------------------
__device__ __forceinline__ void ldsm_x4(uint32_t& r0, uint32_t& r1,
                                        uint32_t& r2, uint32_t& r3,
                                        uint32_t addr) {
    asm volatile("ldmatrix.sync.aligned.m8n8.x4.shared.b16 {%0,%1,%2,%3}, [%4];"
                 : "=r"(r0), "=r"(r1), "=r"(r2), "=r"(r3) : "r"(addr));
}
__device__ __forceinline__ void ldsm_x2(uint32_t& r0, uint32_t& r1,
                                        uint32_t addr) {
    asm volatile("ldmatrix.sync.aligned.m8n8.x2.shared.b16 {%0,%1}, [%2];"
                 : "=r"(r0), "=r"(r1) : "r"(addr));
}
__device__ __forceinline__ void mma_f16(float& c0, float& c1, float& c2, float& c3,
                                        uint32_t a0, uint32_t a1, uint32_t a2, uint32_t a3,
                                        uint32_t b0, uint32_t b1) {
    asm volatile("mma.sync.aligned.m16n8k16.row.col.f32.f16.f16.f32 "
                 "{%0,%1,%2,%3}, {%4,%5,%6,%7}, {%8,%9}, {%0,%1,%2,%3};"
                 : "+f"(c0), "+f"(c1), "+f"(c2), "+f"(c3)
                 : "r"(a0), "r"(a1), "r"(a2), "r"(a3), "r"(b0), "r"(b1));
}

// ---------------------------------------------------------------------------
// Fused Q|K projection GEMM (unchanged from R14).
// ---------------------------------------------------------------------------
#define KP 40

__global__ __launch_bounds__(512) void proj_mma_kernel(const float* __restrict__ hi,
                                                       const float* __restrict__ Qb,
                                                       const float* __restrict__ Kb) {
    const uint4* Wg = (const uint4*)g_wf;

    __shared__ __half As[128][KP];
    __shared__ __half Ws[256][KP];

    const int tid  = threadIdx.x;
    const int lane = tid & 31;
    const int wid  = tid >> 5;
    const int wm   = wid & 3;
    const int wn   = wid >> 2;
    const int m0   = blockIdx.x * 128;

    float c[2][8][4];
#pragma unroll
    for (int mt = 0; mt < 2; mt++)
#pragma unroll
        for (int nt = 0; nt < 8; nt++)
#pragma unroll
            for (int i = 0; i < 4; i++) c[mt][nt][i] = 0.0f;

    const int alrow = tid >> 2;
    const int alq   = tid & 3;
    int arow_g = m0 + alrow;
    if (arow_g >= NN) arow_g = NN - 1;
    const float4* hi4 = (const float4*)hi;
    const size_t a_base = (size_t)arow_g * 64 + alq * 2;

    const int wlrow = tid >> 1;
    const int wlh   = tid & 1;
    const size_t w_base = (size_t)wlrow * 32 + wlh * 2;

    const int a_row  = wm * 32 + (lane & 15);
    const int a_koff = (lane >> 4) * 8;
    const int b_row  = wn * 64 + (lane & 7);
    const int b_koff = ((lane >> 3) & 1) * 8;

    float4 pa0, pa1;
    uint4  pw0, pw1;
    pa0 = hi4[a_base];  pa1 = hi4[a_base + 1];
    pw0 = Wg[w_base];   pw1 = Wg[w_base + 1];

    for (int ch = 0; ch < 8; ch++) {
        {
            uint2 h0 = cvt4(pa0), h1 = cvt4(pa1);
            uint4 v; v.x = h0.x; v.y = h0.y; v.z = h1.x; v.w = h1.y;
            *(uint4*)&As[alrow][alq * 8] = v;
            *(uint4*)&Ws[wlrow][wlh * 16]     = pw0;
            *(uint4*)&Ws[wlrow][wlh * 16 + 8] = pw1;
        }
        __syncthreads();

        if (ch < 7) {
            const int kc4 = (ch + 1) * 8;
            pa0 = hi4[a_base + kc4];
            pa1 = hi4[a_base + kc4 + 1];
            pw0 = Wg[w_base + (ch + 1) * 4];
            pw1 = Wg[w_base + (ch + 1) * 4 + 1];
        }

#pragma unroll
        for (int ks = 0; ks < 2; ks++) {
            const int k0 = ks * 16;
            uint32_t a[2][4];
#pragma unroll
            for (int mt = 0; mt < 2; mt++) {
                uint32_t addr = (uint32_t)__cvta_generic_to_shared(
                    &As[a_row + mt * 16][k0 + a_koff]);
                ldsm_x4(a[mt][0], a[mt][1], a[mt][2], a[mt][3], addr);
            }
#pragma unroll
            for (int nt = 0; nt < 8; nt++) {
                uint32_t b0, b1;
                uint32_t baddr = (uint32_t)__cvta_generic_to_shared(
                    &Ws[b_row + nt * 8][k0 + b_koff]);
                ldsm_x2(b0, b1, baddr);
#pragma unroll
                for (int mt = 0; mt < 2; mt++) {
                    mma_f16(c[mt][nt][0], c[mt][nt][1], c[mt][nt][2], c[mt][nt][3],
                            a[mt][0], a[mt][1], a[mt][2], a[mt][3], b0, b1);
                }
            }
        }
        __syncthreads();
    }

    __half* out        = (wn < 2) ? g_qh : g_kh;
    const float* bias  = (wn < 2) ? Qb   : Kb;
    const int colbase  = (wn & 1) * 64;
#pragma unroll
    for (int nt = 0; nt < 8; nt++) {
        const int col = colbase + nt * 8 + (lane & 3) * 2;
        const float b0 = __ldg(&bias[col]);
        const float b1 = __ldg(&bias[col + 1]);
#pragma unroll
        for (int mt = 0; mt < 2; mt++) {
            const int r0 = m0 + wm * 32 + mt * 16 + (lane >> 2);
            if (r0 < NN) {
                *(__half2*)&out[(size_t)r0 * AD + col] =
                    __floats2half2_rn(c[mt][nt][0] + b0, c[mt][nt][1] + b1);
            }
            const int r1 = r0 + 8;
            if (r1 < NN) {
                *(__half2*)&out[(size_t)r1 * AD + col] =
                    __floats2half2_rn(c[mt][nt][2] + b0, c[mt][nt][3] + b1);
            }
        }
    }
}

// ---------------------------------------------------------------------------
// Edge pass (R15 version — kept): warp per 8 edges, paired-lane LDG.128,
// src index via shuffles (no edge[] reload).
// ---------------------------------------------------------------------------
__global__ __launch_bounds__(256) void edge_kernel(const float* __restrict__ radial,
                                                   const int*  __restrict__ edge,
                                                   const float* __restrict__ Qrw,
                                                   const float* __restrict__ Qrb,
                                                   float* __restrict__ prods) {
    const int lane = threadIdx.x & 31;
    const int gw   = (blockIdx.x * 256 + threadIdx.x) >> 5;
    const int e0   = gw * 8;
    const int side = lane >> 4;
    const int sub  = lane & 15;

    float w8[8], b8[8];
    {
        const float4* w4p = (const float4*)Qrw;
        const float4* b4p = (const float4*)Qrb;
        float4 wa = w4p[sub * 2], wb = w4p[sub * 2 + 1];
        float4 ba = b4p[sub * 2], bb = b4p[sub * 2 + 1];
        w8[0]=wa.x; w8[1]=wa.y; w8[2]=wa.z; w8[3]=wa.w;
        w8[4]=wb.x; w8[5]=wb.y; w8[6]=wb.z; w8[7]=wb.w;
        b8[0]=ba.x; b8[1]=ba.y; b8[2]=ba.z; b8[3]=ba.w;
        b8[4]=bb.x; b8[5]=bb.y; b8[6]=bb.z; b8[7]=bb.w;
    }

    int   msrc[4], mdst[4];
    float mr[4];
#pragma unroll
    for (int s = 0; s < 4; s++) {
        int e = e0 + 2 * s + side;
        msrc[s] = edge[e];
        mdst[s] = edge[NE + e];
        mr[s]   = radial[e];
    }

    uint4 qv[4], kv[4];
#pragma unroll
    for (int s = 0; s < 4; s++) {
        qv[s] = *(const uint4*)(g_qh + (size_t)msrc[s] * AD + sub * 8);
        kv[s] = *(const uint4*)(g_kh + (size_t)mdst[s] * AD + sub * 8);
    }

    float t[4];
#pragma unroll
    for (int s = 0; s < 4; s++) {
        const uint32_t* qw = (const uint32_t*)&qv[s];
        const uint32_t* kw = (const uint32_t*)&kv[s];
        float acc = 0.f;
        const float r = mr[s];
#pragma unroll
        for (int p = 0; p < 4; p++) {
            float2 q2 = __half22float2(*(const __half2*)&qw[p]);
            float2 k2 = __half22float2(*(const __half2*)&kw[p]);
            float s0 = q2.x + fmaf(r, w8[2 * p],     b8[2 * p]);
            float s1 = q2.y + fmaf(r, w8[2 * p + 1], b8[2 * p + 1]);
            acc = fmaf(s0, k2.x, acc);
            acc = fmaf(s1, k2.y, acc);
        }
        acc += __shfl_xor_sync(0xffffffff, acc, 1);
        t[s] = acc;
    }

    // lane l -> (edge e0+4r+j, head l&7), j = l>>3; slot = 2r+(j>>1), side = j&1
    const int j      = lane >> 3;
    const int l_src  = (j & 1) * 16 + 2 * (lane & 7);
    const int l_meta = (j & 1) * 16;
#pragma unroll
    for (int r = 0; r < 2; r++) {
        const float va = __shfl_sync(0xffffffff, t[2 * r],     l_src);
        const float vb = __shfl_sync(0xffffffff, t[2 * r + 1], l_src);
        const float pr = ((j >> 1) ? vb : va) * 0.25f;

        prods[(e0 + 4 * r) * NH + lane] = pr;
        const float ex = __expf(pr);

        const int s0 = __shfl_sync(0xffffffff, msrc[2 * r],     l_meta);
        const int s1 = __shfl_sync(0xffffffff, msrc[2 * r + 1], l_meta);
        const int se = (j >> 1) ? s1 : s0;
        atomicAdd(&g_sum[se * NH + (lane & 7)], ex);
    }
}

// ---------------------------------------------------------------------------
// Norm (reverted to R14 shape — 1 float4 per thread; proven 21.6 us):
// att[e,h] = exp(prods[e,h]) / sum[src,h]
// ---------------------------------------------------------------------------
__global__ void norm_kernel(const int* __restrict__ edge,
                            const float* __restrict__ prods,
                            float* __restrict__ att) {
    int i = blockIdx.x * blockDim.x + threadIdx.x;
    if (i < NE * NH / 4) {
        int e = i >> 1;
        int half = i & 1;
        const float4 s = *(const float4*)&g_sum[edge[e] * NH + half * 4];
        float4 p = ((const float4*)prods)[i];
        float4 a;
        a.x = __fdividef(__expf(p.x), s.x);
        a.y = __fdividef(__expf(p.y), s.y);
        a.z = __fdividef(__expf(p.z), s.z);
        a.w = __fdividef(__expf(p.w), s.w);
        ((float4*)att)[i] = a;
    }
}

// ---------------------------------------------------------------------------
extern "C" void kernel_launch(void* const* d_in, const int* in_sizes, int n_in,
                              void* d_out, int out_size) {
    const float* hi     = (const float*)d_in[0];
    const float* radial = (const float*)d_in[1];
    const float* Qw     = (const float*)d_in[2];
    const float* Qb     = (const float*)d_in[3];
    const float* Qrw    = (const float*)d_in[4];
    const float* Qrb    = (const float*)d_in[5];
    const float* Kw     = (const float*)d_in[6];
    const float* Kb     = (const float*)d_in[7];
    const int*   edge   = (const int*)d_in[8];

    float* out   = (float*)d_out;
    float* att   = out;                       // [E, H]
    float* prods = out + (size_t)NE * NH;     // [E, H]

    prep_kernel<<<(PREP_TOT + 255) / 256, 256>>>(Qw, Kw);
    proj_mma_kernel<<<(NN + 127) / 128, 512>>>(hi, Qb, Kb);
    edge_kernel<<<NE / 64, 256>>>(radial, edge, Qrw, Qrb, prods);
    norm_kernel<<<(NE * NH / 4 + 255) / 256, 256>>>(edge, prods, att);
}